// round 9
// baseline (speedup 1.0000x reference)
#include <cuda_runtime.h>
#include <math.h>

#define BB   64
#define SS   2048
#define DD   1024
#define HH   300
#define OO   2
#define SCH  16                 // s-chunks for the big reduction
#define SPC  (SS / SCH)         // 128 s per chunk
#define D4   (DD / 4)           // 256 float4 per row

// Scratch (allocation-free rule: __device__ globals)
__device__ int   g_end[BB];
__device__ float g_partial[BB][SCH][DD];
__device__ float g_euph[BB][DD];

// ---------------------------------------------------------------------------
// 1) end-index scan (+ seed out with b2 — 2 stores, free).
//    end = first s with ids[b][s]==1, fallback B (reference's except-path).
//    NO other work here: R8 showed fattening this kernel costs more than the
//    launch it saves.
// ---------------------------------------------------------------------------
__global__ __launch_bounds__(1024) void k_end(const int* __restrict__ ids,
                                              const float* __restrict__ b2,
                                              float* __restrict__ out) {
    int b = blockIdx.x;
    int t = threadIdx.x;
    __shared__ int m;
    if (t == 0) m = 0x7fffffff;
    if (t < OO) out[b * OO + t] = b2[t];   // out accumulator starts at bias
    __syncthreads();
    const int2* row = (const int2*)(ids + b * SS);
    int2 v = row[t];                       // 1024 threads * 2 ids = 2048
    if (v.x == 1) atomicMin(&m, 2 * t);
    if (v.y == 1) atomicMin(&m, 2 * t + 1);
    __syncthreads();
    if (t == 0) g_end[b] = (m == 0x7fffffff) ? BB : m;
}

// ---------------------------------------------------------------------------
// 2) big masked segment-sum with COMPACTED row list (R5 win, ~at DRAM cap).
//    Plain STG of partials — R8 proved atomics on this critical-path kernel
//    cost ~4us. Do not fuse anything into this kernel.
// ---------------------------------------------------------------------------
__global__ __launch_bounds__(256) void k_reduce(const float* __restrict__ x,
                                                const float* __restrict__ mask) {
    int b = blockIdx.x;
    int c = blockIdx.y;
    int t = threadIdx.x;
    int end = g_end[b];
    int s0  = c * SPC;

    __shared__ float s_m[SPC];
    __shared__ int   s_idx[SPC];
    __shared__ int   s_cnt;
    if (t == 0) s_cnt = 0;
    __syncthreads();

    if (t < SPC) {                          // first 128 threads stage+compact
        int s = s0 + t;
        float m = (s < end) ? mask[b * SS + s] : 0.0f;
        if (m != 0.0f) {
            int p = atomicAdd(&s_cnt, 1);
            s_idx[p] = t;
            s_m[p]   = m;
        }
    }
    __syncthreads();
    int n = s_cnt;

    const float4* xp = (const float4*)(x + (long long)b * SS * DD)
                       + (long long)s0 * D4 + t;

    float4 acc = make_float4(0.f, 0.f, 0.f, 0.f);
    int i = 0;
    for (; i + 4 <= n; i += 4) {
        int   j0 = s_idx[i],     j1 = s_idx[i + 1];
        int   j2 = s_idx[i + 2], j3 = s_idx[i + 3];
        float m0 = s_m[i],       m1 = s_m[i + 1];
        float m2 = s_m[i + 2],   m3 = s_m[i + 3];
        float4 v0 = xp[j0 * D4];
        float4 v1 = xp[j1 * D4];
        float4 v2 = xp[j2 * D4];
        float4 v3 = xp[j3 * D4];
        acc.x += v0.x * m0; acc.y += v0.y * m0; acc.z += v0.z * m0; acc.w += v0.w * m0;
        acc.x += v1.x * m1; acc.y += v1.y * m1; acc.z += v1.z * m1; acc.w += v1.w * m1;
        acc.x += v2.x * m2; acc.y += v2.y * m2; acc.z += v2.z * m2; acc.w += v2.w * m2;
        acc.x += v3.x * m3; acc.y += v3.y * m3; acc.z += v3.z * m3; acc.w += v3.w * m3;
    }
    for (; i < n; i++) {
        int   j = s_idx[i];
        float m = s_m[i];
        float4 v = xp[j * D4];
        acc.x += v.x * m; acc.y += v.y * m; acc.z += v.z * m; acc.w += v.w * m;
    }
    ((float4*)g_partial[b][c])[t] = acc;
}

// ---------------------------------------------------------------------------
// 3) fold the SCH partials and divide by end. Grid (64 b, 4 q) = 256 blocks.
// ---------------------------------------------------------------------------
__global__ __launch_bounds__(256) void k_combine() {
    int b = blockIdx.x;
    int d = blockIdx.y * 256 + threadIdx.x;
    float inv = 1.0f / (float)g_end[b];
    float acc = 0.f;
#pragma unroll
    for (int c = 0; c < SCH; c++)
        acc += g_partial[b][c][d];
    g_euph[b][d] = acc * inv;
}

// ---------------------------------------------------------------------------
// 4) fused hidden+out: warp owns h, W1 row in regs, 4 batches per warp
//    (grid (16,75)=1200 blocks — measured sweet spot: 9.3us). Each hidden
//    value is consumed immediately: lane 0 adds tanh(..)*W2[o][h] into
//    out[b][o] via REDG (out pre-seeded with b2). Kills the k_out launch.
// ---------------------------------------------------------------------------
__global__ __launch_bounds__(128) void k_hidden(const float* __restrict__ W1,
                                                const float* __restrict__ b1,
                                                const float* __restrict__ W2,
                                                float* __restrict__ out) {
    int warp = threadIdx.x >> 5;
    int lane = threadIdx.x & 31;
    int h    = blockIdx.y * 4 + warp;          // 75*4 = 300, always valid
    int b0   = blockIdx.x * 4;                 // 16*4  = 64

    const float4* w4p = (const float4*)(W1 + (long long)h * DD);
    float4 w[8];
#pragma unroll
    for (int i = 0; i < 8; i++) w[i] = w4p[lane + 32 * i];
    float bias = b1[h];
    float w2a  = W2[h];                        // W2[0][h]
    float w2b  = W2[HH + h];                   // W2[1][h]

#pragma unroll
    for (int bi = 0; bi < 4; bi++) {
        int b = b0 + bi;
        const float4* e4 = (const float4*)g_euph[b];
        float s = 0.f;
#pragma unroll
        for (int i = 0; i < 8; i++) {
            float4 e = e4[lane + 32 * i];
            s += e.x * w[i].x + e.y * w[i].y + e.z * w[i].z + e.w * w[i].w;
        }
#pragma unroll
        for (int off = 16; off > 0; off >>= 1)
            s += __shfl_xor_sync(0xffffffffu, s, off);
        if (lane == 0) {
            float hv = tanhf(s + bias);
            atomicAdd(&out[b * OO + 0], hv * w2a);
            atomicAdd(&out[b * OO + 1], hv * w2b);
        }
    }
}

// ---------------------------------------------------------------------------
extern "C" void kernel_launch(void* const* d_in, const int* in_sizes, int n_in,
                              void* d_out, int out_size) {
    const float* x    = (const float*)d_in[0];       // [B,S,D] f32
    const int*   ids  = (const int*)d_in[1];         // [B,S]   i32 (JAX x64 off)
    const float* mask = (const float*)d_in[2];       // [B,S,1] f32
    const float* W1   = (const float*)d_in[3];       // [H,D]
    const float* b1   = (const float*)d_in[4];       // [H]
    const float* W2   = (const float*)d_in[5];       // [OUT,H]
    const float* b2   = (const float*)d_in[6];       // [OUT]
    float*       out  = (float*)d_out;               // [B,OUT]

    k_end    <<<BB, 1024>>>(ids, b2, out);
    k_reduce <<<dim3(BB, SCH), 256>>>(x, mask);
    k_combine<<<dim3(BB, 4), 256>>>();
    k_hidden <<<dim3(16, HH / 4), 128>>>(W1, b1, W2, out);
}

// round 10
// speedup vs baseline: 1.1800x; 1.1800x over previous
#include <cuda_runtime.h>
#include <math.h>

#define BB   64
#define SS   2048
#define DD   1024
#define HH   300
#define OO   2
#define SCH  16                 // s-chunks for the big reduction
#define SPC  (SS / SCH)         // 128 s per chunk
#define D4   (DD / 4)           // 256 float4 per row

// Scratch (allocation-free rule: __device__ globals)
__device__ int   g_end[BB];
__device__ float g_partial[BB][SCH][DD];
__device__ float g_euph[BB][DD];
__device__ float g_hidden[BB][HH];

// ---------------------------------------------------------------------------
// 1) end-index scan. end = first s with ids[b][s]==1, fallback B (reference's
//    except-path quirk). 1024 threads, int2 loads, single pass.
// ---------------------------------------------------------------------------
__global__ __launch_bounds__(1024) void k_end(const int* __restrict__ ids) {
    int b = blockIdx.x;
    int t = threadIdx.x;
    __shared__ int m;
    if (t == 0) m = 0x7fffffff;
    __syncthreads();
    const int2* row = (const int2*)(ids + b * SS);
    int2 v = row[t];                       // 1024 threads * 2 ids = 2048
    if (v.x == 1) atomicMin(&m, 2 * t);
    if (v.y == 1) atomicMin(&m, 2 * t + 1);
    __syncthreads();
    if (t == 0) g_end[b] = (m == 0x7fffffff) ? BB : m;
}

// ---------------------------------------------------------------------------
// 2) big masked segment-sum with COMPACTED row list (~at DRAM/LTS cap).
//    Plain STG of partials — R8/R9 proved global fp atomics regress badly.
//    Do not fuse anything into this kernel (R4).
// ---------------------------------------------------------------------------
__global__ __launch_bounds__(256) void k_reduce(const float* __restrict__ x,
                                                const float* __restrict__ mask) {
    int b = blockIdx.x;
    int c = blockIdx.y;
    int t = threadIdx.x;
    int end = g_end[b];
    int s0  = c * SPC;

    __shared__ float s_m[SPC];
    __shared__ int   s_idx[SPC];
    __shared__ int   s_cnt;
    if (t == 0) s_cnt = 0;
    __syncthreads();

    if (t < SPC) {                          // first 128 threads stage+compact
        int s = s0 + t;
        float m = (s < end) ? mask[b * SS + s] : 0.0f;
        if (m != 0.0f) {
            int p = atomicAdd(&s_cnt, 1);
            s_idx[p] = t;
            s_m[p]   = m;
        }
    }
    __syncthreads();
    int n = s_cnt;

    const float4* xp = (const float4*)(x + (long long)b * SS * DD)
                       + (long long)s0 * D4 + t;

    float4 acc = make_float4(0.f, 0.f, 0.f, 0.f);
    int i = 0;
    for (; i + 4 <= n; i += 4) {
        int   j0 = s_idx[i],     j1 = s_idx[i + 1];
        int   j2 = s_idx[i + 2], j3 = s_idx[i + 3];
        float m0 = s_m[i],       m1 = s_m[i + 1];
        float m2 = s_m[i + 2],   m3 = s_m[i + 3];
        float4 v0 = xp[j0 * D4];
        float4 v1 = xp[j1 * D4];
        float4 v2 = xp[j2 * D4];
        float4 v3 = xp[j3 * D4];
        acc.x += v0.x * m0; acc.y += v0.y * m0; acc.z += v0.z * m0; acc.w += v0.w * m0;
        acc.x += v1.x * m1; acc.y += v1.y * m1; acc.z += v1.z * m1; acc.w += v1.w * m1;
        acc.x += v2.x * m2; acc.y += v2.y * m2; acc.z += v2.z * m2; acc.w += v2.w * m2;
        acc.x += v3.x * m3; acc.y += v3.y * m3; acc.z += v3.z * m3; acc.w += v3.w * m3;
    }
    for (; i < n; i++) {
        int   j = s_idx[i];
        float m = s_m[i];
        float4 v = xp[j * D4];
        acc.x += v.x * m; acc.y += v.y * m; acc.z += v.z * m; acc.w += v.w * m;
    }
    ((float4*)g_partial[b][c])[t] = acc;
}

// ---------------------------------------------------------------------------
// 3) fold the SCH partials and divide by end. Grid (64 b, 4 q) = 256 blocks.
// ---------------------------------------------------------------------------
__global__ __launch_bounds__(256) void k_combine() {
    int b = blockIdx.x;
    int d = blockIdx.y * 256 + threadIdx.x;
    float inv = 1.0f / (float)g_end[b];
    float acc = 0.f;
#pragma unroll
    for (int c = 0; c < SCH; c++)
        acc += g_partial[b][c][d];
    g_euph[b][d] = acc * inv;
}

// ---------------------------------------------------------------------------
// 4) hidden = tanh(euph @ W1^T + b1).  Grid (32 bTiles, 75 hGroups) = 2400
//    blocks — doubling parallelism vs the 1200-block/9.3us point (occ was
//    only 50%, issue 26%); W1-row register reuse x2 keeps L2 traffic ~38MB.
//    Plain store to g_hidden; NO out atomics (R9: +13.5us).
// ---------------------------------------------------------------------------
__global__ __launch_bounds__(128) void k_hidden(const float* __restrict__ W1,
                                                const float* __restrict__ b1) {
    int warp = threadIdx.x >> 5;
    int lane = threadIdx.x & 31;
    int h    = blockIdx.y * 4 + warp;          // 75*4 = 300, always valid
    int b0   = blockIdx.x * 2;                 // 32*2  = 64

    const float4* w4p = (const float4*)(W1 + (long long)h * DD);
    float4 w[8];
#pragma unroll
    for (int i = 0; i < 8; i++) w[i] = w4p[lane + 32 * i];
    float bias = b1[h];

#pragma unroll
    for (int bi = 0; bi < 2; bi++) {
        const float4* e4 = (const float4*)g_euph[b0 + bi];
        float s = 0.f;
#pragma unroll
        for (int i = 0; i < 8; i++) {
            float4 e = e4[lane + 32 * i];
            s += e.x * w[i].x + e.y * w[i].y + e.z * w[i].z + e.w * w[i].w;
        }
#pragma unroll
        for (int off = 16; off > 0; off >>= 1)
            s += __shfl_xor_sync(0xffffffffu, s, off);
        if (lane == 0)
            g_hidden[b0 + bi][h] = tanhf(s + bias);
    }
}

// ---------------------------------------------------------------------------
// 5) out = hidden @ W2^T + b2.  Warp per (b, o): 128 warps over 8 blocks.
// ---------------------------------------------------------------------------
__global__ __launch_bounds__(512) void k_out(const float* __restrict__ W2,
                                             const float* __restrict__ b2,
                                             float* __restrict__ out) {
    int gw   = blockIdx.x * 16 + (threadIdx.x >> 5);   // 0..127
    int lane = threadIdx.x & 31;
    int b    = gw >> 1;
    int o    = gw & 1;

    const float* hid = g_hidden[b];
    const float* w   = W2 + o * HH;
    float s = 0.f;
#pragma unroll 5
    for (int k = lane; k < HH; k += 32)
        s += hid[k] * w[k];
#pragma unroll
    for (int off = 16; off > 0; off >>= 1)
        s += __shfl_xor_sync(0xffffffffu, s, off);
    if (lane == 0)
        out[b * OO + o] = s + b2[o];
}

// ---------------------------------------------------------------------------
extern "C" void kernel_launch(void* const* d_in, const int* in_sizes, int n_in,
                              void* d_out, int out_size) {
    const float* x    = (const float*)d_in[0];       // [B,S,D] f32
    const int*   ids  = (const int*)d_in[1];         // [B,S]   i32 (JAX x64 off)
    const float* mask = (const float*)d_in[2];       // [B,S,1] f32
    const float* W1   = (const float*)d_in[3];       // [H,D]
    const float* b1   = (const float*)d_in[4];       // [H]
    const float* W2   = (const float*)d_in[5];       // [OUT,H]
    const float* b2   = (const float*)d_in[6];       // [OUT]
    float*       out  = (float*)d_out;               // [B,OUT]

    k_end    <<<BB, 1024>>>(ids);
    k_reduce <<<dim3(BB, SCH), 256>>>(x, mask);
    k_combine<<<dim3(BB, 4), 256>>>();
    k_hidden <<<dim3(32, HH / 4), 128>>>(W1, b1);
    k_out    <<<8, 512>>>(W2, b2, out);
}

// round 11
// speedup vs baseline: 1.2432x; 1.0536x over previous
#include <cuda_runtime.h>
#include <math.h>

#define BB   64
#define SS   2048
#define DD   1024
#define HH   300
#define OO   2
#define SCH  16                 // s-chunks for the big reduction
#define SPC  (SS / SCH)         // 128 s per chunk
#define D4   (DD / 4)           // 256 float4 per row

// Scratch (allocation-free rule: __device__ globals)
__device__ int   g_end[BB];
__device__ float g_partial[BB][SCH][DD];
__device__ float g_euph[BB][DD];
__device__ float g_hidden[BB][HH];

// ---------------------------------------------------------------------------
// 1) end-index scan. end = first s with ids[b][s]==1, fallback B (reference's
//    except-path quirk). 1024 threads, int2 loads, single pass.
// ---------------------------------------------------------------------------
__global__ __launch_bounds__(1024) void k_end(const int* __restrict__ ids) {
    int b = blockIdx.x;
    int t = threadIdx.x;
    __shared__ int m;
    if (t == 0) m = 0x7fffffff;
    __syncthreads();
    const int2* row = (const int2*)(ids + b * SS);
    int2 v = row[t];                       // 1024 threads * 2 ids = 2048
    if (v.x == 1) atomicMin(&m, 2 * t);
    if (v.y == 1) atomicMin(&m, 2 * t + 1);
    __syncthreads();
    if (t == 0) g_end[b] = (m == 0x7fffffff) ? BB : m;
}

// ---------------------------------------------------------------------------
// 2) big masked segment-sum with COMPACTED row list (~at DRAM/LTS cap).
//    PDL: raw mask chunk is loaded BEFORE the grid-dependency sync on g_end,
//    overlapping with k_end. Plain STG of partials (atomics regress: R8/R9).
// ---------------------------------------------------------------------------
__global__ __launch_bounds__(256) void k_reduce(const float* __restrict__ x,
                                                const float* __restrict__ mask) {
    int b = blockIdx.x;
    int c = blockIdx.y;
    int t = threadIdx.x;
    int s0 = c * SPC;

    // independent preamble: raw mask load (does not need g_end)
    float mraw = 0.0f;
    if (t < SPC) mraw = mask[b * SS + s0 + t];

    cudaGridDependencySynchronize();       // wait for k_end's g_end
    int end = g_end[b];

    __shared__ float s_m[SPC];
    __shared__ int   s_idx[SPC];
    __shared__ int   s_cnt;
    if (t == 0) s_cnt = 0;
    __syncthreads();

    if (t < SPC && (s0 + t) < end && mraw != 0.0f) {
        int p = atomicAdd(&s_cnt, 1);
        s_idx[p] = t;
        s_m[p]   = mraw;
    }
    __syncthreads();
    int n = s_cnt;

    const float4* xp = (const float4*)(x + (long long)b * SS * DD)
                       + (long long)s0 * D4 + t;

    float4 acc = make_float4(0.f, 0.f, 0.f, 0.f);
    int i = 0;
    for (; i + 4 <= n; i += 4) {
        int   j0 = s_idx[i],     j1 = s_idx[i + 1];
        int   j2 = s_idx[i + 2], j3 = s_idx[i + 3];
        float m0 = s_m[i],       m1 = s_m[i + 1];
        float m2 = s_m[i + 2],   m3 = s_m[i + 3];
        float4 v0 = xp[j0 * D4];
        float4 v1 = xp[j1 * D4];
        float4 v2 = xp[j2 * D4];
        float4 v3 = xp[j3 * D4];
        acc.x += v0.x * m0; acc.y += v0.y * m0; acc.z += v0.z * m0; acc.w += v0.w * m0;
        acc.x += v1.x * m1; acc.y += v1.y * m1; acc.z += v1.z * m1; acc.w += v1.w * m1;
        acc.x += v2.x * m2; acc.y += v2.y * m2; acc.z += v2.z * m2; acc.w += v2.w * m2;
        acc.x += v3.x * m3; acc.y += v3.y * m3; acc.z += v3.z * m3; acc.w += v3.w * m3;
    }
    for (; i < n; i++) {
        int   j = s_idx[i];
        float m = s_m[i];
        float4 v = xp[j * D4];
        acc.x += v.x * m; acc.y += v.y * m; acc.z += v.z * m; acc.w += v.w * m;
    }
    ((float4*)g_partial[b][c])[t] = acc;
}

// ---------------------------------------------------------------------------
// 3) fold the SCH partials and divide by end. Grid (64 b, 4 q) = 256 blocks.
//    PDL: sync at top just hides the launch gap.
// ---------------------------------------------------------------------------
__global__ __launch_bounds__(256) void k_combine() {
    int b = blockIdx.x;
    int d = blockIdx.y * 256 + threadIdx.x;
    cudaGridDependencySynchronize();
    float inv = 1.0f / (float)g_end[b];
    float acc = 0.f;
#pragma unroll
    for (int c = 0; c < SCH; c++)
        acc += g_partial[b][c][d];
    g_euph[b][d] = acc * inv;
}

// ---------------------------------------------------------------------------
// 4) hidden = tanh(euph @ W1^T + b1).  Grid (32,75)=2400 blocks (measured
//    optimum 8.7us). PDL: the 16KB/block W1 register load happens BEFORE the
//    sync on g_euph -> overlaps with k_combine's execution.
// ---------------------------------------------------------------------------
__global__ __launch_bounds__(128) void k_hidden(const float* __restrict__ W1,
                                                const float* __restrict__ b1) {
    int warp = threadIdx.x >> 5;
    int lane = threadIdx.x & 31;
    int h    = blockIdx.y * 4 + warp;          // 75*4 = 300, always valid
    int b0   = blockIdx.x * 2;                 // 32*2  = 64

    // independent preamble: W1 row + bias (inputs, not produced upstream)
    const float4* w4p = (const float4*)(W1 + (long long)h * DD);
    float4 w[8];
#pragma unroll
    for (int i = 0; i < 8; i++) w[i] = w4p[lane + 32 * i];
    float bias = b1[h];

    cudaGridDependencySynchronize();           // wait for g_euph

#pragma unroll
    for (int bi = 0; bi < 2; bi++) {
        const float4* e4 = (const float4*)g_euph[b0 + bi];
        float s = 0.f;
#pragma unroll
        for (int i = 0; i < 8; i++) {
            float4 e = e4[lane + 32 * i];
            s += e.x * w[i].x + e.y * w[i].y + e.z * w[i].z + e.w * w[i].w;
        }
#pragma unroll
        for (int off = 16; off > 0; off >>= 1)
            s += __shfl_xor_sync(0xffffffffu, s, off);
        if (lane == 0)
            g_hidden[b0 + bi][h] = tanhf(s + bias);
    }
}

// ---------------------------------------------------------------------------
// 5) out = hidden @ W2^T + b2.  Warp per (b, o): 128 warps over 8 blocks.
//    PDL: W2 slice loaded pre-sync.
// ---------------------------------------------------------------------------
__global__ __launch_bounds__(512) void k_out(const float* __restrict__ W2,
                                             const float* __restrict__ b2,
                                             float* __restrict__ out) {
    int gw   = blockIdx.x * 16 + (threadIdx.x >> 5);   // 0..127
    int lane = threadIdx.x & 31;
    int b    = gw >> 1;
    int o    = gw & 1;

    const float* w = W2 + o * HH;
    float wr[10];                              // ceil(300/32)=10 per lane
#pragma unroll
    for (int i = 0; i < 10; i++) {
        int k = lane + 32 * i;
        wr[i] = (k < HH) ? w[k] : 0.0f;
    }
    float bias = b2[o];

    cudaGridDependencySynchronize();           // wait for g_hidden

    const float* hid = g_hidden[b];
    float s = 0.f;
#pragma unroll
    for (int i = 0; i < 10; i++) {
        int k = lane + 32 * i;
        if (k < HH) s += hid[k] * wr[i];
    }
#pragma unroll
    for (int off = 16; off > 0; off >>= 1)
        s += __shfl_xor_sync(0xffffffffu, s, off);
    if (lane == 0)
        out[b * OO + o] = s + bias;
}

// ---------------------------------------------------------------------------
template <typename... Args>
static inline void launch_pdl(void (*kern)(Args...), dim3 grid, dim3 block,
                              Args... args) {
    cudaLaunchConfig_t cfg = {};
    cfg.gridDim  = grid;
    cfg.blockDim = block;
    cudaLaunchAttribute attr[1];
    attr[0].id = cudaLaunchAttributeProgrammaticStreamSerialization;
    attr[0].val.programmaticStreamSerializationAllowed = 1;
    cfg.attrs    = attr;
    cfg.numAttrs = 1;
    cudaLaunchKernelEx(&cfg, kern, args...);
}

extern "C" void kernel_launch(void* const* d_in, const int* in_sizes, int n_in,
                              void* d_out, int out_size) {
    const float* x    = (const float*)d_in[0];       // [B,S,D] f32
    const int*   ids  = (const int*)d_in[1];         // [B,S]   i32 (JAX x64 off)
    const float* mask = (const float*)d_in[2];       // [B,S,1] f32
    const float* W1   = (const float*)d_in[3];       // [H,D]
    const float* b1   = (const float*)d_in[4];       // [H]
    const float* W2   = (const float*)d_in[5];       // [OUT,H]
    const float* b2   = (const float*)d_in[6];       // [OUT]
    float*       out  = (float*)d_out;               // [B,OUT]

    k_end<<<BB, 1024>>>(ids);
    launch_pdl(k_reduce,  dim3(BB, SCH), dim3(256), x, mask);
    launch_pdl(k_combine, dim3(BB, 4),   dim3(256));
    launch_pdl(k_hidden,  dim3(32, HH / 4), dim3(128), W1, b1);
    launch_pdl(k_out,     dim3(8), dim3(512), W2, b2, out);
}